// round 12
// baseline (speedup 1.0000x reference)
#include <cuda_runtime.h>

// deblurNet: out = x @ W.T with W complex DIAGONAL:
//   out[b,i] = (xr + j*xi)[b,i] * W[i,i]
//
// Scatter-count curve flattened (295K->6.88us, 74K->6.66, 18K->6.62):
// remaining time = launch ramp + latency-bound body (all data L2-resident
// across graph replays). R12: keep minimal scatter (each diag entry
// gathered once chip-wide = 18,432 loads) but finer blocks: 1152 x 128,
// TC=8. Barrier spans 4 warps (less wait on slowest gather), and the
// re+im gather is packed into ONE warp-instruction (threads 0-7 load wr,
// 8-15 load wi).

#define TOT   589824   // B*N complex elements (64 * 9216)
#define NDIM  9216     // N = 96*96
#define DSTR  9217     // diagonal stride in dense [N,N] f32 storage
#define BATCH 64
#define TC    8                // columns per block (gathered ONCE chip-wide)
#define NBLK  (NDIM / TC)      // 1152 blocks

__global__ void __launch_bounds__(128)
deblur_tiled3(const float* __restrict__ xr,
              const float* __restrict__ xi,
              const float* __restrict__ wr,
              const float* __restrict__ wi,
              float* __restrict__ out,
              int mode) {
    __shared__ float s_re[TC];
    __shared__ float s_im[TC];

    const int tid  = threadIdx.x;
    const int col0 = blockIdx.x * TC;

    // Phase 1a: diag gather, one warp-instruction for re+im.
    // threads 0-7: wr[col0+t], threads 8-15: wi[col0+t-8].
    // Max offset (NDIM-1)*DSTR = N^2-1: in-bounds.
    if (tid < 2 * TC) {
        const int c = tid & (TC - 1);
        const float* base = (tid < TC) ? wr : wi;
        const float v = __ldg(base + (long long)(col0 + c) * DSTR);
        if (tid < TC) s_re[c] = v; else s_im[c] = v;
    }

    // Phase 1b: prefetch x BEFORE the barrier (independent of the gather,
    // so BAR release waits on max(gather, x-load), not the sum).
    const int cg = tid & 1;                // 2 quad-groups -> 8 cols
    const int b  = tid >> 1;               // 0..63 batch row
    const int i   = col0 + cg * 4;
    const int idx = b * NDIM + i;          // max TOT-4: in-bounds
    const float4 ar = *reinterpret_cast<const float4*>(xr + idx);
    const float4 ai = *reinterpret_cast<const float4*>(xi + idx);

    __syncthreads();

    // Phase 2: broadcast smem reads (64 b-threads share each cg -> N=1).
    const int c0 = cg * 4;
    const float w0r = s_re[c0 + 0], w0i = s_im[c0 + 0];
    const float w1r = s_re[c0 + 1], w1i = s_im[c0 + 1];
    const float w2r = s_re[c0 + 2], w2i = s_im[c0 + 2];
    const float w3r = s_re[c0 + 3], w3i = s_im[c0 + 3];

    const float o0r = fmaf(ar.x, w0r, -ai.x * w0i), o0i = fmaf(ar.x, w0i, ai.x * w0r);
    const float o1r = fmaf(ar.y, w1r, -ai.y * w1i), o1i = fmaf(ar.y, w1i, ai.y * w1r);
    const float o2r = fmaf(ar.z, w2r, -ai.z * w2i), o2i = fmaf(ar.z, w2i, ai.z * w2r);
    const float o3r = fmaf(ar.w, w3r, -ai.w * w3i), o3i = fmaf(ar.w, w3i, ai.w * w3r);

    if (mode == 1) {
        // Interleaved re/im (f32 view of complex64): 2*TOT floats.
        float4* o = reinterpret_cast<float4*>(out) + (idx >> 1);
        o[0] = make_float4(o0r, o0i, o1r, o1i);
        o[1] = make_float4(o2r, o2i, o3r, o3i);
    } else {
        // Real part only: TOT floats.
        *reinterpret_cast<float4*>(out + idx) = make_float4(o0r, o1r, o2r, o3r);
    }
}

extern "C" void kernel_launch(void* const* d_in, const int* in_sizes, int n_in,
                              void* d_out, int out_size) {
    if (n_in < 4) return;

    // Inputs are f32 at reported element counts (confirmed R6-R11 passes).
    // Smaller-size pair = x (B*N), larger pair = W (N*N); real before imag.
    long long smin = -1;
    for (int k = 0; k < 4; ++k) {
        long long s = (long long)in_sizes[k];
        if (smin < 0 || s < smin) smin = s;
    }
    const float* xs[2] = {nullptr, nullptr};
    const float* ws[2] = {nullptr, nullptr};
    int nx = 0, nw = 0;
    for (int k = 0; k < 4; ++k) {
        if ((long long)in_sizes[k] == smin && nx < 2) xs[nx++] = (const float*)d_in[k];
        else if (nw < 2)                              ws[nw++] = (const float*)d_in[k];
    }
    if (nx < 2 || nw < 2) return;

    // Output mode strictly bounded by out_size (4-byte elements).
    const int mode = ((long long)out_size >= 2LL * TOT) ? 1 : 0;

    deblur_tiled3<<<NBLK, 128>>>(xs[0], xs[1], ws[0], ws[1],
                                 (float*)d_out, mode);   // 1152 blocks
}